// round 3
// baseline (speedup 1.0000x reference)
#include <cuda_runtime.h>
#include <math.h>

#define BB 256
#define SS 512
#define DD 32
#define HH 512
#define GG 2048   // 4*HH
#define PLEN 24
#define NB 128    // persistent blocks (<=148 SMs -> all co-resident)

// ---------------- scratch (__device__ globals; no allocation) ----------------
__device__ float g_enc_outs[BB * SS * HH];          // 268 MB
__device__ float g_enc_proj[BB * SS * HH];          // 268 MB
__device__ float g_h0[2][BB * HH];
__device__ float g_h1[2][BB * HH];
__device__ float g_c0[BB * HH];
__device__ float g_c1[BB * HH];
__device__ float g_W0[GG * 544];                    // [ew0 | eu0], gate-interleaved rows
__device__ float g_W1[GG * 1024];                   // [ew1 | eu1]
__device__ float g_Wd0[GG * 1025];                  // [dw0 | du0]
__device__ float g_Wd1[GG * 1024];                  // [dw1 | du1]
__device__ float g_b0[GG], g_b1[GG], g_bd0[GG], g_bd1[GG];
__device__ float g_dp[BB * HH];
__device__ float g_sc[BB * SS];
__device__ float g_wsm[BB * SS];
__device__ float g_xcat[BB * 513];
__device__ float g_decin[BB];
__device__ float g_hist[BB];

// grid-wide barrier state
__device__ unsigned int g_bar_count = 0;
__device__ volatile unsigned int g_bar_gen = 0;

__device__ __forceinline__ void grid_barrier() {
    __syncthreads();
    if (threadIdx.x == 0) {
        __threadfence();
        unsigned int gen = g_bar_gen;
        if (atomicAdd(&g_bar_count, 1u) == NB - 1u) {
            g_bar_count = 0;
            __threadfence();
            g_bar_gen = gen + 1u;
        } else {
            while (g_bar_gen == gen) { __nanosleep(32); }
        }
        __threadfence();
    }
    __syncthreads();
}

__device__ __forceinline__ float fast_tanh(float x) {
    float y;
    asm("tanh.approx.f32 %0, %1;" : "=f"(y) : "f"(x));
    return y;
}

// ---------------- weight prep: gate-interleave + concat ----------------
__global__ void prep_w(float* __restrict__ dst, const float* __restrict__ Wa, int Ka,
                       const float* __restrict__ Wb, int Kb) {
    int Kt = Ka + Kb;
    int idx = blockIdx.x * 256 + threadIdx.x;
    if (idx >= GG * Kt) return;
    int np = idx / Kt;
    int k = idx - np * Kt;
    int q = np & 3;
    int j = np >> 2;
    int n = q * HH + j;
    float v;
    if (k < Ka) v = Wa[(size_t)n * Ka + k];
    else        v = Wb[(size_t)n * Kb + (k - Ka)];
    dst[idx] = v;
}

__global__ void prep_b(float* __restrict__ dst, const float* __restrict__ bi,
                       const float* __restrict__ bh) {
    int np = blockIdx.x * 256 + threadIdx.x;
    if (np >= GG) return;
    int q = np & 3;
    int j = np >> 2;
    int n = q * HH + j;
    dst[np] = bi[n] + bh[n];
}

__global__ void zero_init(const float* __restrict__ src) {
    int i = blockIdx.x * 256 + threadIdx.x;
    if (i < BB * HH) { g_h0[0][i] = 0.f; g_h1[0][i] = 0.f; g_c0[i] = 0.f; g_c1[i] = 0.f; }
    if (i < BB) {
        size_t base = (size_t)i * SS * DD + (size_t)(SS - 1) * DD;
        g_decin[i] = src[base + (DD - 1)];   // src[:, -1, -1]
        g_hist[i]  = src[base + (DD - 15)];  // src[:, -1, -15]
    }
}

// ---------------- tile GEMM + fused LSTM cell (device fn) ----------------
// gates[b, n'] = sum_k [A1|A2][b,k] * W[n',k] + bias[n'],  n' = 4j+q interleaved.
__device__ __forceinline__ void gemm_lstm_tile(
    int tn, int tm,
    const float* __restrict__ A1, int lda1, int K1,
    const float* __restrict__ A2, int lda2, int K2,
    const float* __restrict__ W, int ldw,
    const float* __restrict__ bias,
    float* __restrict__ c_state,
    float* __restrict__ h_out,
    float* __restrict__ h_extra, size_t extra_stride,
    float (*As)[68], float (*Wsh)[68])
{
    const int tid = threadIdx.x;
    const int tx = tid & 15;
    const int ty = tid >> 4;
    const int lk = tid & 15;
    const int lr = tid >> 4;
    const int bn = tn * 64;
    const int bm = tm * 64;
    const int Kt = K1 + K2;

    float acc[4][4];
#pragma unroll
    for (int i = 0; i < 4; i++)
#pragma unroll
        for (int j = 0; j < 4; j++) acc[i][j] = 0.f;

    float ra[4], rw[4];
    {
        int gk = lk;
#pragma unroll
        for (int pp = 0; pp < 4; pp++) {
            int m = bm + lr + 16 * pp;
            float v = 0.f;
            if (gk < K1)       v = A1[(size_t)m * lda1 + gk];
            else if (gk < Kt)  v = A2[(size_t)m * lda2 + (gk - K1)];
            ra[pp] = v;
            int n = bn + lr + 16 * pp;
            rw[pp] = (gk < Kt) ? W[(size_t)n * ldw + gk] : 0.f;
        }
    }

    for (int k0 = 0; k0 < Kt; k0 += 16) {
#pragma unroll
        for (int pp = 0; pp < 4; pp++) {
            As[lk][lr + 16 * pp] = ra[pp];
            Wsh[lk][lr + 16 * pp] = rw[pp];
        }
        __syncthreads();
        if (k0 + 16 < Kt) {
            int gk = k0 + 16 + lk;
#pragma unroll
            for (int pp = 0; pp < 4; pp++) {
                int m = bm + lr + 16 * pp;
                float v = 0.f;
                if (gk < K1)       v = A1[(size_t)m * lda1 + gk];
                else if (gk < Kt)  v = A2[(size_t)m * lda2 + (gk - K1)];
                ra[pp] = v;
                int n = bn + lr + 16 * pp;
                rw[pp] = (gk < Kt) ? W[(size_t)n * ldw + gk] : 0.f;
            }
        }
#pragma unroll
        for (int kk = 0; kk < 16; kk++) {
            float4 a = *(const float4*)&As[kk][4 * ty];
            float4 w = *(const float4*)&Wsh[kk][4 * tx];
            acc[0][0] += a.x * w.x; acc[0][1] += a.x * w.y; acc[0][2] += a.x * w.z; acc[0][3] += a.x * w.w;
            acc[1][0] += a.y * w.x; acc[1][1] += a.y * w.y; acc[1][2] += a.y * w.z; acc[1][3] += a.y * w.w;
            acc[2][0] += a.z * w.x; acc[2][1] += a.z * w.y; acc[2][2] += a.z * w.z; acc[2][3] += a.z * w.w;
            acc[3][0] += a.w * w.x; acc[3][1] += a.w * w.y; acc[3][2] += a.w * w.z; acc[3][3] += a.w * w.w;
        }
        __syncthreads();
    }

    const int ncol = bn + 4 * tx;
    const int j = ncol >> 2;
#pragma unroll
    for (int i = 0; i < 4; i++) {
        int b = bm + 4 * ty + i;
        float gi = acc[i][0] + bias[ncol + 0];
        float gf = acc[i][1] + bias[ncol + 1];
        float gg = acc[i][2] + bias[ncol + 2];
        float go = acc[i][3] + bias[ncol + 3];
        gi = 1.f / (1.f + expf(-gi));
        gf = 1.f / (1.f + expf(-gf));
        gg = tanhf(gg);
        go = 1.f / (1.f + expf(-go));
        float c = gf * c_state[b * HH + j] + gi * gg;
        c_state[b * HH + j] = c;
        float h = go * tanhf(c);
        h_out[b * HH + j] = h;
        if (h_extra) h_extra[(size_t)b * extra_stride + j] = h;
    }
}

// ---------------- plain tile GEMM: C[m,n] = sum_k A[m,k]*W[n,k] (+bias) ----------------
__device__ __forceinline__ void gemm_bias_tile(
    int tn, int tm,
    const float* __restrict__ A, int lda,
    const float* __restrict__ W, int ldw,
    const float* __restrict__ bias,
    float* __restrict__ C, int N, int K,
    float (*As)[68], float (*Wsh)[68])
{
    const int tid = threadIdx.x;
    const int tx = tid & 15;
    const int ty = tid >> 4;
    const int lk = tid & 15;
    const int lr = tid >> 4;
    const int bn = tn * 64;
    const int bm = tm * 64;

    float acc[4][4];
#pragma unroll
    for (int i = 0; i < 4; i++)
#pragma unroll
        for (int j = 0; j < 4; j++) acc[i][j] = 0.f;

    float ra[4], rw[4];
    {
        int gk = lk;
#pragma unroll
        for (int pp = 0; pp < 4; pp++) {
            int m = bm + lr + 16 * pp;
            ra[pp] = (gk < K) ? A[(size_t)m * lda + gk] : 0.f;
            int n = bn + lr + 16 * pp;
            rw[pp] = (gk < K) ? W[(size_t)n * ldw + gk] : 0.f;
        }
    }
    for (int k0 = 0; k0 < K; k0 += 16) {
#pragma unroll
        for (int pp = 0; pp < 4; pp++) {
            As[lk][lr + 16 * pp] = ra[pp];
            Wsh[lk][lr + 16 * pp] = rw[pp];
        }
        __syncthreads();
        if (k0 + 16 < K) {
            int gk = k0 + 16 + lk;
#pragma unroll
            for (int pp = 0; pp < 4; pp++) {
                int m = bm + lr + 16 * pp;
                ra[pp] = (gk < K) ? A[(size_t)m * lda + gk] : 0.f;
                int n = bn + lr + 16 * pp;
                rw[pp] = (gk < K) ? W[(size_t)n * ldw + gk] : 0.f;
            }
        }
#pragma unroll
        for (int kk = 0; kk < 16; kk++) {
            float4 a = *(const float4*)&As[kk][4 * ty];
            float4 w = *(const float4*)&Wsh[kk][4 * tx];
            acc[0][0] += a.x * w.x; acc[0][1] += a.x * w.y; acc[0][2] += a.x * w.z; acc[0][3] += a.x * w.w;
            acc[1][0] += a.y * w.x; acc[1][1] += a.y * w.y; acc[1][2] += a.y * w.z; acc[1][3] += a.y * w.w;
            acc[2][0] += a.z * w.x; acc[2][1] += a.z * w.y; acc[2][2] += a.z * w.z; acc[2][3] += a.z * w.w;
            acc[3][0] += a.w * w.x; acc[3][1] += a.w * w.y; acc[3][2] += a.w * w.z; acc[3][3] += a.w * w.w;
        }
        __syncthreads();
    }
#pragma unroll
    for (int i = 0; i < 4; i++) {
        int m = bm + 4 * ty + i;
#pragma unroll
        for (int jj = 0; jj < 4; jj++) {
            int n = bn + 4 * tx + jj;
            float v = acc[i][jj];
            if (bias) v += bias[n];
            C[(size_t)m * N + n] = v;
        }
    }
}

// ---------------- persistent mega-kernel ----------------
__global__ __launch_bounds__(256, 1) void mega(
    const float* __restrict__ src,
    const float* __restrict__ attn_W,
    const float* __restrict__ attn_b,
    const float* __restrict__ v_W,
    const float* __restrict__ fc_W,
    const float* __restrict__ fc_b,
    float* __restrict__ out)
{
    __shared__ __align__(16) float As[16][68];
    __shared__ __align__(16) float Wsh[16][68];
    __shared__ float sm[1024];

    const int bid = blockIdx.x;
    const int tid = threadIdx.x;
    const int tn = bid & 31;   // 32 n-tiles (N=2048)
    const int tm = bid >> 5;   // 4 m-tiles  (M=256)

    // ---------------- encoder: 512 steps, ONE grid barrier per step ----------------
    for (int t = 0; t < SS; t++) {
        int p = t & 1;
        gemm_lstm_tile(tn, tm, src + t * DD, SS * DD, DD,
                       g_h0[p], HH, HH, g_W0, 544, g_b0,
                       g_c0, g_h0[p ^ 1], nullptr, 0, As, Wsh);
        grid_barrier();  // h0(t) complete; L1(t) and L0(t+1) are conflict-free afterwards
        gemm_lstm_tile(tn, tm, g_h0[p ^ 1], HH, HH,
                       g_h1[p], HH, HH, g_W1, 1024, g_b1,
                       g_c1, g_h1[p ^ 1],
                       g_enc_outs + (size_t)t * HH, (size_t)SS * HH, As, Wsh);
    }
    grid_barrier();  // enc_outs + final states complete

    // ---------------- enc_proj = enc_outs @ W_enc^T + attn_b ----------------
    // tiles: (BB*SS/64) x (HH/64) = 2048 x 8 = 16384
    for (int tt = bid; tt < 16384; tt += NB) {
        gemm_bias_tile(tt & 7, tt >> 3, g_enc_outs, HH, attn_W, 2 * HH,
                       attn_b, g_enc_proj, HH, HH, As, Wsh);
    }
    grid_barrier();

    // ---------------- decoder: 24 steps ----------------
    for (int it = 0; it < PLEN; it++) {
        int p = it & 1;

        // A: dp = h1 @ W_dec^T   (8 x 4 = 32 tiles)
        if (bid < 32) {
            gemm_bias_tile(bid & 7, bid >> 3, g_h1[p], HH, attn_W + HH, 2 * HH,
                           nullptr, g_dp, HH, HH, As, Wsh);
        }
        grid_barrier();

        // B: scores[b,s] = sum_h v[h]*tanh(ep[b,s,h]+dp[b,h]) — 2 b per block
        {
            int warp = tid >> 5, lane = tid & 31;
#pragma unroll 1
            for (int bb = 0; bb < 2; bb++) {
                int b = bid * 2 + bb;
                for (int i = tid; i < HH; i += 256) {
                    sm[i] = g_dp[b * HH + i];
                    sm[512 + i] = v_W[i];
                }
                __syncthreads();
                const float* ep = g_enc_proj + (size_t)b * SS * HH;
                for (int s = warp; s < SS; s += 8) {
                    const float* row = ep + (size_t)s * HH;
                    float acc = 0.f;
#pragma unroll 4
                    for (int h = lane; h < HH; h += 32)
                        acc += sm[512 + h] * fast_tanh(row[h] + sm[h]);
#pragma unroll
                    for (int off = 16; off > 0; off >>= 1)
                        acc += __shfl_down_sync(0xffffffffu, acc, off);
                    if (lane == 0) g_sc[b * SS + s] = acc;
                }
                __syncthreads();
            }
        }
        grid_barrier();

        // C: softmax over s — 2 b per block
        {
#pragma unroll 1
            for (int bb = 0; bb < 2; bb++) {
                int b = bid * 2 + bb;
                float m = -1e30f;
                for (int s = tid; s < SS; s += 256) m = fmaxf(m, g_sc[b * SS + s]);
                sm[tid] = m; __syncthreads();
                for (int off = 128; off > 0; off >>= 1) {
                    if (tid < off) sm[tid] = fmaxf(sm[tid], sm[tid + off]);
                    __syncthreads();
                }
                m = sm[0]; __syncthreads();
                float sum = 0.f;
                for (int s = tid; s < SS; s += 256) {
                    float e = expf(g_sc[b * SS + s] - m);
                    g_wsm[b * SS + s] = e;
                    sum += e;
                }
                sm[tid] = sum; __syncthreads();
                for (int off = 128; off > 0; off >>= 1) {
                    if (tid < off) sm[tid] += sm[tid + off];
                    __syncthreads();
                }
                float inv = 1.f / sm[0]; __syncthreads();
                for (int s = tid; s < SS; s += 256) g_wsm[b * SS + s] *= inv;
            }
        }
        grid_barrier();

        // D: context -> xcat[:,1:513]; xcat[:,0] = dec_in — 2 b per block
        {
#pragma unroll 1
            for (int bb = 0; bb < 2; bb++) {
                int b = bid * 2 + bb;
                for (int i = tid; i < SS; i += 256) sm[i] = g_wsm[b * SS + i];
                __syncthreads();
                const float* base = g_enc_outs + (size_t)b * SS * HH;
                float a0 = 0.f, a1 = 0.f;
#pragma unroll 4
                for (int s = 0; s < SS; s++) {
                    const float* r = base + (size_t)s * HH;
                    a0 += sm[s] * r[tid];
                    a1 += sm[s] * r[tid + 256];
                }
                g_xcat[b * 513 + 1 + tid] = a0;
                g_xcat[b * 513 + 1 + tid + 256] = a1;
                if (tid == 0) g_xcat[b * 513] = g_decin[b];
                __syncthreads();
            }
        }
        grid_barrier();

        // E: decoder LSTM layer 0 (K = 513)
        gemm_lstm_tile(tn, tm, g_xcat, 513, 513,
                       g_h0[p], HH, HH, g_Wd0, 1025, g_bd0,
                       g_c0, g_h0[p ^ 1], nullptr, 0, As, Wsh);
        grid_barrier();

        // F: decoder LSTM layer 1 (K = 1024)
        gemm_lstm_tile(tn, tm, g_h0[p ^ 1], HH, HH,
                       g_h1[p], HH, HH, g_Wd1, 1024, g_bd1,
                       g_c1, g_h1[p ^ 1], nullptr, 0, As, Wsh);
        grid_barrier();

        // G: pred + decin update (32 blocks x 8 warps = 256 b)
        if (bid < 32) {
            int warp = tid >> 5, lane = tid & 31;
            int b = bid * 8 + warp;
            const float* h1r = g_h1[p ^ 1] + b * HH;
            float acc = 0.f;
            for (int h = lane; h < HH; h += 32) acc += h1r[h] * fc_W[h];
#pragma unroll
            for (int off = 16; off > 0; off >>= 1)
                acc += __shfl_down_sync(0xffffffffu, acc, off);
            if (lane == 0) {
                float pred = acc + fc_b[0];
                out[b * PLEN + it] = pred;
                g_decin[b] = 0.8f * pred + 0.2f * g_hist[b];
            }
        }
        // no barrier needed here: the barrier after next step's stage A orders
        // G(t)'s decin write before D(t+1)'s read; dp overwrite in A(t+1) is
        // ordered after B(t) by the C/D/E/F barriers of step t.
    }
}

// ---------------- launch ----------------
extern "C" void kernel_launch(void* const* d_in, const int* in_sizes, int n_in,
                              void* d_out, int out_size) {
    (void)in_sizes; (void)n_in; (void)out_size;
    const float* src    = (const float*)d_in[0];
    const float* ew0    = (const float*)d_in[1];
    const float* eu0    = (const float*)d_in[2];
    const float* ebi0   = (const float*)d_in[3];
    const float* ebh0   = (const float*)d_in[4];
    const float* ew1    = (const float*)d_in[5];
    const float* eu1    = (const float*)d_in[6];
    const float* ebi1   = (const float*)d_in[7];
    const float* ebh1   = (const float*)d_in[8];
    const float* dw0    = (const float*)d_in[9];
    const float* du0    = (const float*)d_in[10];
    const float* dbi0   = (const float*)d_in[11];
    const float* dbh0   = (const float*)d_in[12];
    const float* dw1    = (const float*)d_in[13];
    const float* du1    = (const float*)d_in[14];
    const float* dbi1   = (const float*)d_in[15];
    const float* dbh1   = (const float*)d_in[16];
    const float* attn_W = (const float*)d_in[17];
    const float* attn_b = (const float*)d_in[18];
    const float* v_W    = (const float*)d_in[19];
    const float* fc_W   = (const float*)d_in[20];
    const float* fc_b   = (const float*)d_in[21];
    float* out = (float*)d_out;

    float *W0, *W1, *Wd0, *Wd1, *b0, *b1, *bd0, *bd1;
    cudaGetSymbolAddress((void**)&W0, g_W0);
    cudaGetSymbolAddress((void**)&W1, g_W1);
    cudaGetSymbolAddress((void**)&Wd0, g_Wd0);
    cudaGetSymbolAddress((void**)&Wd1, g_Wd1);
    cudaGetSymbolAddress((void**)&b0, g_b0);
    cudaGetSymbolAddress((void**)&b1, g_b1);
    cudaGetSymbolAddress((void**)&bd0, g_bd0);
    cudaGetSymbolAddress((void**)&bd1, g_bd1);

    // weight prep (recomputed each launch; deterministic)
    prep_w<<<(GG * 544 + 255) / 256, 256>>>(W0, ew0, DD, eu0, HH);
    prep_w<<<(GG * 1024 + 255) / 256, 256>>>(W1, ew1, HH, eu1, HH);
    prep_w<<<(GG * 1025 + 255) / 256, 256>>>(Wd0, dw0, HH + 1, du0, HH);
    prep_w<<<(GG * 1024 + 255) / 256, 256>>>(Wd1, dw1, HH, du1, HH);
    prep_b<<<(GG + 255) / 256, 256>>>(b0, ebi0, ebh0);
    prep_b<<<(GG + 255) / 256, 256>>>(b1, ebi1, ebh1);
    prep_b<<<(GG + 255) / 256, 256>>>(bd0, dbi0, dbh0);
    prep_b<<<(GG + 255) / 256, 256>>>(bd1, dbi1, dbh1);
    zero_init<<<(BB * HH + 255) / 256, 256>>>(src);

    mega<<<NB, 256>>>(src, attn_W, attn_b, v_W, fc_W, fc_b, out);
}